// round 1
// baseline (speedup 1.0000x reference)
#include <cuda_runtime.h>
#include <math.h>

// Problem constants
#define Bb 4
#define Cc 256
#define Nn 4096          // H*W = 64*64
#define Oo 320           // 32 (q) + 32 (k) + 256 (v), packed per pixel

// Scratch: qkv[b][n][o]  (q at o=0..31, k at 32..63, v at 64..319)
__device__ float g_qkv[Bb * Nn * Oo];   // 20 MB

// ---------------------------------------------------------------------------
// Kernel 1: fused QKV projection.  out[b][n][o] = W_o . x[b][:][n] + bias_o
// Tiled GEMM: CTA tile 64 n x 64 o, K-tile 32, per-thread 4x4 micro-tile.
// ---------------------------------------------------------------------------
__global__ __launch_bounds__(256)
void proj_kernel(const float* __restrict__ x,
                 const float* __restrict__ Wq, const float* __restrict__ bq,
                 const float* __restrict__ Wk, const float* __restrict__ bk,
                 const float* __restrict__ Wv, const float* __restrict__ bv)
{
    __shared__ float Xs[32 * 68];   // [kc 32][n 64] pad->68
    __shared__ float Ws[32 * 68];   // [kc 32][o 64] pad->68

    const int t  = threadIdx.x;
    const int tx = t & 15;          // n micro index
    const int ty = t >> 4;          // o micro index
    const int n0 = blockIdx.x * 64;
    const int o0 = blockIdx.y * 64;
    const int b  = blockIdx.z;

    const float* xb = x + b * Cc * Nn;

    float acc[4][4];
#pragma unroll
    for (int i = 0; i < 4; ++i)
#pragma unroll
        for (int j = 0; j < 4; ++j) acc[i][j] = 0.f;

    for (int kc = 0; kc < Cc; kc += 32) {
        // Load X tile: x[b][kc+cc][n0+nn]  (coalesced in n)
#pragma unroll
        for (int i = 0; i < 8; ++i) {
            int idx = t + i * 256;
            int cc  = idx >> 6;
            int nn  = idx & 63;
            Xs[cc * 68 + nn] = xb[(kc + cc) * Nn + n0 + nn];
        }
        // Load W tile transposed: Ws[cc][oo] = Wrow(o0+oo)[kc+cc]
#pragma unroll
        for (int i = 0; i < 8; ++i) {
            int idx = t + i * 256;
            int oo  = idx >> 5;
            int cc  = idx & 31;
            int o   = o0 + oo;
            const float* wr = (o < 32) ? (Wq + o * Cc)
                             : (o < 64) ? (Wk + (o - 32) * Cc)
                                        : (Wv + (o - 64) * Cc);
            Ws[cc * 68 + oo] = wr[kc + cc];
        }
        __syncthreads();

        const float4* X4 = reinterpret_cast<const float4*>(Xs);
        const float4* W4 = reinterpret_cast<const float4*>(Ws);
#pragma unroll
        for (int cc = 0; cc < 32; ++cc) {
            float4 a = X4[cc * 17 + tx];
            float4 w = W4[cc * 17 + ty];
            acc[0][0] = fmaf(a.x, w.x, acc[0][0]);
            acc[0][1] = fmaf(a.x, w.y, acc[0][1]);
            acc[0][2] = fmaf(a.x, w.z, acc[0][2]);
            acc[0][3] = fmaf(a.x, w.w, acc[0][3]);
            acc[1][0] = fmaf(a.y, w.x, acc[1][0]);
            acc[1][1] = fmaf(a.y, w.y, acc[1][1]);
            acc[1][2] = fmaf(a.y, w.z, acc[1][2]);
            acc[1][3] = fmaf(a.y, w.w, acc[1][3]);
            acc[2][0] = fmaf(a.z, w.x, acc[2][0]);
            acc[2][1] = fmaf(a.z, w.y, acc[2][1]);
            acc[2][2] = fmaf(a.z, w.z, acc[2][2]);
            acc[2][3] = fmaf(a.z, w.w, acc[2][3]);
            acc[3][0] = fmaf(a.w, w.x, acc[3][0]);
            acc[3][1] = fmaf(a.w, w.y, acc[3][1]);
            acc[3][2] = fmaf(a.w, w.z, acc[3][2]);
            acc[3][3] = fmaf(a.w, w.w, acc[3][3]);
        }
        __syncthreads();
    }

    // Epilogue: bias + store (float4 along o; 4 consecutive o never cross q/k/v
    // boundaries because regions are 32-aligned).
    const int o = o0 + ty * 4;
    float4 bias;
    if (o < 32)      bias = *reinterpret_cast<const float4*>(bq + o);
    else if (o < 64) bias = *reinterpret_cast<const float4*>(bk + (o - 32));
    else             bias = *reinterpret_cast<const float4*>(bv + (o - 64));

#pragma unroll
    for (int i = 0; i < 4; ++i) {
        float4 st;
        st.x = acc[i][0] + bias.x;
        st.y = acc[i][1] + bias.y;
        st.z = acc[i][2] + bias.z;
        st.w = acc[i][3] + bias.w;
        int n = n0 + tx * 4 + i;
        *reinterpret_cast<float4*>(&g_qkv[(b * Nn + n) * Oo + o]) = st;
    }
}

// ---------------------------------------------------------------------------
// Kernel 2: flash attention + gamma residual.
// One CTA = one (batch, 64-query tile). 256 threads.
//   score role : thread -> (qi = t/4, cq = t%4), 16 keys each
//   PV role    : thread -> channel c = t, acc[64] queries in registers
// ---------------------------------------------------------------------------
__global__ __launch_bounds__(256)
void attn_kernel(const float* __restrict__ x,
                 const float* __restrict__ gamma,
                 float* __restrict__ out)
{
    __shared__ float Qs[64 * 36];    // [query][d 32] pad->36
    __shared__ float Ks[64 * 36];    // [key][d 32]   pad->36
    __shared__ float Pb[64 * 68];    // [query][key 64] pad->68
    __shared__ float rs[64];         // per-row correction / final scale

    const int t  = threadIdx.x;
    const int qi = t >> 2;
    const int cq = t & 3;
    const int n0 = blockIdx.x * 64;
    const int b  = blockIdx.y;
    const float* qkv_b = g_qkv + b * Nn * Oo;

    // Load Q tile once (64 rows x 32 floats = 512 float4)
#pragma unroll
    for (int i = 0; i < 2; ++i) {
        int idx = t + i * 256;
        int row = idx >> 3;
        int d4  = idx & 7;
        float4 v = *reinterpret_cast<const float4*>(qkv_b + (n0 + row) * Oo + d4 * 4);
        *reinterpret_cast<float4*>(&Qs[row * 36 + d4 * 4]) = v;
    }

    float acc[64];
#pragma unroll
    for (int i = 0; i < 64; ++i) acc[i] = 0.f;
    float m_run = -3.0e38f;
    float l_run = 0.f;

    for (int kt = 0; kt < 64; ++kt) {
        const int m0 = kt * 64;

        // Load K tile
#pragma unroll
        for (int i = 0; i < 2; ++i) {
            int idx = t + i * 256;
            int row = idx >> 3;
            int d4  = idx & 7;
            float4 v = *reinterpret_cast<const float4*>(qkv_b + (m0 + row) * Oo + 32 + d4 * 4);
            *reinterpret_cast<float4*>(&Ks[row * 36 + d4 * 4]) = v;
        }
        __syncthreads();   // K tile ready (also fences prev-iter P reads)

        // ---- scores: this thread covers keys mk = cq + 4*j ----
        float s[16];
        const float4* Q4 = reinterpret_cast<const float4*>(Qs);
        const float4* K4 = reinterpret_cast<const float4*>(Ks);
#pragma unroll
        for (int j = 0; j < 16; ++j) {
            int mk = cq + 4 * j;
            float sum = 0.f;
#pragma unroll
            for (int d = 0; d < 8; ++d) {
                float4 kk = K4[mk * 9 + d];
                float4 qq = Q4[qi * 9 + d];
                sum = fmaf(qq.x, kk.x, sum);
                sum = fmaf(qq.y, kk.y, sum);
                sum = fmaf(qq.z, kk.z, sum);
                sum = fmaf(qq.w, kk.w, sum);
            }
            s[j] = sum;
        }

        // ---- online softmax (row = quad of 4 lanes) ----
        float tmax = s[0];
#pragma unroll
        for (int j = 1; j < 16; ++j) tmax = fmaxf(tmax, s[j]);
        tmax = fmaxf(tmax, __shfl_xor_sync(0xffffffffu, tmax, 1));
        tmax = fmaxf(tmax, __shfl_xor_sync(0xffffffffu, tmax, 2));

        float m_new = fmaxf(m_run, tmax);
        float corr  = __expf(m_run - m_new);
        float psum  = 0.f;
#pragma unroll
        for (int j = 0; j < 16; ++j) {
            float p = __expf(s[j] - m_new);
            s[j] = p;
            psum += p;
        }
        psum += __shfl_xor_sync(0xffffffffu, psum, 1);
        psum += __shfl_xor_sync(0xffffffffu, psum, 2);
        l_run = l_run * corr + psum;
        m_run = m_new;

#pragma unroll
        for (int j = 0; j < 16; ++j)
            Pb[qi * 68 + cq + 4 * j] = s[j];
        if (cq == 0) rs[qi] = corr;
        __syncthreads();   // P + corr ready

        // ---- PV: thread = channel t; acc over 64 queries ----
#pragma unroll
        for (int q2 = 0; q2 < 64; ++q2) acc[q2] *= rs[q2];

        const float* vp = qkv_b + m0 * Oo + 64 + t;
        float a0 = vp[0];
        float a1 = vp[Oo];
        float a2 = vp[2 * Oo];
        float a3 = vp[3 * Oo];
        const float4* P4 = reinterpret_cast<const float4*>(Pb);

        for (int mg = 0; mg < 16; ++mg) {
            float w0 = a0, w1 = a1, w2 = a2, w3 = a3;
            if (mg + 1 < 16) {
                const float* np = vp + (mg + 1) * 4 * Oo;
                a0 = np[0];
                a1 = np[Oo];
                a2 = np[2 * Oo];
                a3 = np[3 * Oo];
            }
#pragma unroll
            for (int q2 = 0; q2 < 64; ++q2) {
                float4 p4 = P4[q2 * 17 + mg];   // full-warp broadcast LDS.128
                acc[q2] = fmaf(p4.x, w0,
                          fmaf(p4.y, w1,
                          fmaf(p4.z, w2,
                          fmaf(p4.w, w3, acc[q2]))));
            }
        }
        // no trailing sync: next iter's post-K-load sync fences P/rs reuse
    }

    // ---- finalize: scale = gamma / l, residual add ----
    __syncthreads();                   // all PV reads of rs done
    if (cq == 0) rs[qi] = l_run;
    __syncthreads();
    const float g = gamma[0];
    if (t < 64) rs[t] = g / rs[t];
    __syncthreads();

    const float* xp = x   + (b * Cc + t) * Nn + n0;
    float*       op = out + (b * Cc + t) * Nn + n0;
#pragma unroll
    for (int q2 = 0; q2 < 64; q2 += 4) {
        float4 xv = *reinterpret_cast<const float4*>(xp + q2);
        float4 st;
        st.x = fmaf(acc[q2 + 0], rs[q2 + 0], xv.x);
        st.y = fmaf(acc[q2 + 1], rs[q2 + 1], xv.y);
        st.z = fmaf(acc[q2 + 2], rs[q2 + 2], xv.z);
        st.w = fmaf(acc[q2 + 3], rs[q2 + 3], xv.w);
        *reinterpret_cast<float4*>(op + q2) = st;
    }
}

// ---------------------------------------------------------------------------
// Launch
// Inputs (metadata order): x, Wq, bq, Wk, bk, Wv, bv, gamma
// ---------------------------------------------------------------------------
extern "C" void kernel_launch(void* const* d_in, const int* in_sizes, int n_in,
                              void* d_out, int out_size)
{
    const float* x     = (const float*)d_in[0];
    const float* Wq    = (const float*)d_in[1];
    const float* bq    = (const float*)d_in[2];
    const float* Wk    = (const float*)d_in[3];
    const float* bk    = (const float*)d_in[4];
    const float* Wv    = (const float*)d_in[5];
    const float* bv    = (const float*)d_in[6];
    const float* gamma = (const float*)d_in[7];
    float* out = (float*)d_out;

    dim3 pgrid(Nn / 64, Oo / 64, Bb);   // 64 x 5 x 4
    proj_kernel<<<pgrid, 256>>>(x, Wq, bq, Wk, bk, Wv, bv);

    dim3 agrid(Nn / 64, Bb);            // 64 x 4
    attn_kernel<<<agrid, 256>>>(x, gamma, out);
}

// round 5
// speedup vs baseline: 4.5251x; 4.5251x over previous
#include <cuda_runtime.h>
#include <math.h>

// Problem constants
#define Bb 4
#define Cc 256
#define Nn 4096          // H*W = 64*64
#define Oo 320           // 32 (q) + 32 (k) + 256 (v), packed per pixel

// Scratch: qkv[b][n][o]  (q at o=0..31, k at 32..63, v at 64..319)
__device__ float g_qkv[Bb * Nn * Oo];   // 20 MB

// ---------------------------------------------------------------------------
// tf32 helpers
// ---------------------------------------------------------------------------
__device__ __forceinline__ unsigned f2tf32(float f) {
    unsigned r;
    asm("cvt.rna.tf32.f32 %0, %1;" : "=r"(r) : "f"(f));
    return r;
}
__device__ __forceinline__ float f2tf32f(float f) {
    return __uint_as_float(f2tf32(f));
}

// D(16x8) += A(16x8,row) * B(8x8,col)   -- tf32, fp32 accum
__device__ __forceinline__ void mma_tf32(float d[4], const unsigned a[4],
                                         unsigned b0, unsigned b1) {
    asm volatile(
        "mma.sync.aligned.m16n8k8.row.col.f32.tf32.tf32.f32 "
        "{%0,%1,%2,%3}, {%4,%5,%6,%7}, {%8,%9}, {%0,%1,%2,%3};\n"
        : "+f"(d[0]), "+f"(d[1]), "+f"(d[2]), "+f"(d[3])
        : "r"(a[0]), "r"(a[1]), "r"(a[2]), "r"(a[3]), "r"(b0), "r"(b1));
}

// ---------------------------------------------------------------------------
// Kernel 1: fused QKV projection (fp32 GEMM, unchanged from R1 — ~90us)
// ---------------------------------------------------------------------------
__global__ __launch_bounds__(256)
void proj_kernel(const float* __restrict__ x,
                 const float* __restrict__ Wq, const float* __restrict__ bq,
                 const float* __restrict__ Wk, const float* __restrict__ bk,
                 const float* __restrict__ Wv, const float* __restrict__ bv)
{
    __shared__ float Xs[32 * 68];
    __shared__ float Ws[32 * 68];

    const int t  = threadIdx.x;
    const int tx = t & 15;
    const int ty = t >> 4;
    const int n0 = blockIdx.x * 64;
    const int o0 = blockIdx.y * 64;
    const int b  = blockIdx.z;

    const float* xb = x + b * Cc * Nn;

    float acc[4][4];
#pragma unroll
    for (int i = 0; i < 4; ++i)
#pragma unroll
        for (int j = 0; j < 4; ++j) acc[i][j] = 0.f;

    for (int kc = 0; kc < Cc; kc += 32) {
#pragma unroll
        for (int i = 0; i < 8; ++i) {
            int idx = t + i * 256;
            int cc  = idx >> 6;
            int nn  = idx & 63;
            Xs[cc * 68 + nn] = xb[(kc + cc) * Nn + n0 + nn];
        }
#pragma unroll
        for (int i = 0; i < 8; ++i) {
            int idx = t + i * 256;
            int oo  = idx >> 5;
            int cc  = idx & 31;
            int o   = o0 + oo;
            const float* wr = (o < 32) ? (Wq + o * Cc)
                             : (o < 64) ? (Wk + (o - 32) * Cc)
                                        : (Wv + (o - 64) * Cc);
            Ws[cc * 68 + oo] = wr[kc + cc];
        }
        __syncthreads();

        const float4* X4 = reinterpret_cast<const float4*>(Xs);
        const float4* W4 = reinterpret_cast<const float4*>(Ws);
#pragma unroll
        for (int cc = 0; cc < 32; ++cc) {
            float4 a = X4[cc * 17 + tx];
            float4 w = W4[cc * 17 + ty];
            acc[0][0] = fmaf(a.x, w.x, acc[0][0]);
            acc[0][1] = fmaf(a.x, w.y, acc[0][1]);
            acc[0][2] = fmaf(a.x, w.z, acc[0][2]);
            acc[0][3] = fmaf(a.x, w.w, acc[0][3]);
            acc[1][0] = fmaf(a.y, w.x, acc[1][0]);
            acc[1][1] = fmaf(a.y, w.y, acc[1][1]);
            acc[1][2] = fmaf(a.y, w.z, acc[1][2]);
            acc[1][3] = fmaf(a.y, w.w, acc[1][3]);
            acc[2][0] = fmaf(a.z, w.x, acc[2][0]);
            acc[2][1] = fmaf(a.z, w.y, acc[2][1]);
            acc[2][2] = fmaf(a.z, w.z, acc[2][2]);
            acc[2][3] = fmaf(a.z, w.w, acc[2][3]);
            acc[3][0] = fmaf(a.w, w.x, acc[3][0]);
            acc[3][1] = fmaf(a.w, w.y, acc[3][1]);
            acc[3][2] = fmaf(a.w, w.z, acc[3][2]);
            acc[3][3] = fmaf(a.w, w.w, acc[3][3]);
        }
        __syncthreads();
    }

    const int o = o0 + ty * 4;
    float4 bias;
    if (o < 32)      bias = *reinterpret_cast<const float4*>(bq + o);
    else if (o < 64) bias = *reinterpret_cast<const float4*>(bk + (o - 32));
    else             bias = *reinterpret_cast<const float4*>(bv + (o - 64));

#pragma unroll
    for (int i = 0; i < 4; ++i) {
        float4 st;
        st.x = acc[i][0] + bias.x;
        st.y = acc[i][1] + bias.y;
        st.z = acc[i][2] + bias.z;
        st.w = acc[i][3] + bias.w;
        int n = n0 + tx * 4 + i;
        *reinterpret_cast<float4*>(&g_qkv[(b * Nn + n) * Oo + o]) = st;
    }
}

// ---------------------------------------------------------------------------
// Kernel 2: flash attention on tensor cores (tf32 mma.sync), O^T formulation.
// CTA = 64 queries, 128 threads (4 warps), 2 CTAs/SM.
//   S phase : warp w computes S rows [16w,16w+16) x 64 keys (Q regs x Ks smem)
//   PV phase: warp w owns channels [64w,64w+64), O^T = V^T * P^T
// Smem strides chosen conflict-free: Vs=264, Ks=36, Pb=68 (all ≡ {8,4,4} mod 32)
// ---------------------------------------------------------------------------
#define TQ 64
#define TK 64
#define VS_STR 264
#define KS_STR 36
#define PB_STR 68
#define OFF_V 0
#define OFF_K (OFF_V + TK * VS_STR)
#define OFF_P (OFF_K + TK * KS_STR)
#define OFF_R (OFF_P + TQ * PB_STR)
#define SMEM_FLOATS (OFF_R + 64)
#define SMEM_BYTES (SMEM_FLOATS * 4)

__global__ void __launch_bounds__(128, 2)
attn_kernel(const float* __restrict__ x,
            const float* __restrict__ gamma,
            float* __restrict__ out)
{
    extern __shared__ float sm[];
    float* Vs = sm + OFF_V;
    float* Ks = sm + OFF_K;
    float* Pb = sm + OFF_P;
    float* rs = sm + OFF_R;

    const int t    = threadIdx.x;
    const int w    = t >> 5;
    const int lane = t & 31;
    const int gid  = lane >> 2;   // groupID
    const int tig  = lane & 3;    // thread-in-group
    const int n0   = blockIdx.x * TQ;
    const int b    = blockIdx.y;
    const float* qkv_b = g_qkv + (size_t)b * Nn * Oo;

    // Q fragments for this warp's 16 score rows (held all kernel).
    unsigned qf[4][4];
    {
        const int r0 = n0 + 16 * w + gid;
#pragma unroll
        for (int ks = 0; ks < 4; ++ks) {
            const int c0 = 8 * ks + tig;
            qf[ks][0] = f2tf32(qkv_b[(size_t)r0 * Oo + c0]);
            qf[ks][1] = f2tf32(qkv_b[(size_t)(r0 + 8) * Oo + c0]);
            qf[ks][2] = f2tf32(qkv_b[(size_t)r0 * Oo + c0 + 4]);
            qf[ks][3] = f2tf32(qkv_b[(size_t)(r0 + 8) * Oo + c0 + 4]);
        }
    }

    // O^T accumulators: [mb 4][nt 8][frag 4]  rows c = 64w+16mb+gid(+8),
    // cols q = 8nt + 2tig + {0,1}
    float acc[4][8][4];
#pragma unroll
    for (int mb = 0; mb < 4; ++mb)
#pragma unroll
        for (int nt = 0; nt < 8; ++nt)
#pragma unroll
            for (int j = 0; j < 4; ++j) acc[mb][nt][j] = 0.f;

    float mr0 = -1e30f, mr1 = -1e30f, lr0 = 0.f, lr1 = 0.f;

    for (int kt = 0; kt < Nn / TK; ++kt) {
        const int mk0 = kt * TK;
        __syncthreads();   // Vs/Ks/Pb from previous tile fully consumed

        // ---- stage V tile [64 keys][256 c] (raw fp32 bits; HW truncates) ----
#pragma unroll
        for (int i = 0; i < 32; ++i) {
            int idx = t + 128 * i;
            int key = idx >> 6;
            int c4  = idx & 63;
            float4 v = *reinterpret_cast<const float4*>(
                qkv_b + (size_t)(mk0 + key) * Oo + 64 + c4 * 4);
            *reinterpret_cast<float4*>(Vs + key * VS_STR + c4 * 4) = v;
        }
        // ---- stage K tile [64 keys][32 d] with rna tf32 rounding ----
#pragma unroll
        for (int i = 0; i < 4; ++i) {
            int idx = t + 128 * i;
            int key = idx >> 3;
            int d4  = idx & 7;
            float4 v = *reinterpret_cast<const float4*>(
                qkv_b + (size_t)(mk0 + key) * Oo + 32 + d4 * 4);
            v.x = f2tf32f(v.x); v.y = f2tf32f(v.y);
            v.z = f2tf32f(v.z); v.w = f2tf32f(v.w);
            *reinterpret_cast<float4*>(Ks + key * KS_STR + d4 * 4) = v;
        }
        __syncthreads();

        // ---- S = Q * K^T (warp-local 16x64) ----
        float s[8][4];
#pragma unroll
        for (int nt = 0; nt < 8; ++nt) {
            s[nt][0] = s[nt][1] = s[nt][2] = s[nt][3] = 0.f;
#pragma unroll
            for (int ks = 0; ks < 4; ++ks) {
                const int kr = (8 * nt + gid) * KS_STR + 8 * ks + tig;
                unsigned b0 = __float_as_uint(Ks[kr]);
                unsigned b1 = __float_as_uint(Ks[kr + 4]);
                mma_tf32(s[nt], qf[ks], b0, b1);
            }
        }

        // ---- online softmax (rows r0=16w+gid, r1=r0+8) ----
        float t0 = -1e30f, t1 = -1e30f;
#pragma unroll
        for (int nt = 0; nt < 8; ++nt) {
            t0 = fmaxf(t0, fmaxf(s[nt][0], s[nt][1]));
            t1 = fmaxf(t1, fmaxf(s[nt][2], s[nt][3]));
        }
        t0 = fmaxf(t0, __shfl_xor_sync(0xffffffffu, t0, 1));
        t0 = fmaxf(t0, __shfl_xor_sync(0xffffffffu, t0, 2));
        t1 = fmaxf(t1, __shfl_xor_sync(0xffffffffu, t1, 1));
        t1 = fmaxf(t1, __shfl_xor_sync(0xffffffffu, t1, 2));

        const float nm0 = fmaxf(mr0, t0), nm1 = fmaxf(mr1, t1);
        const float corr0 = __expf(mr0 - nm0), corr1 = __expf(mr1 - nm1);
        float ps0 = 0.f, ps1 = 0.f;
        const int r0 = 16 * w + gid;
#pragma unroll
        for (int nt = 0; nt < 8; ++nt) {
            float p0 = __expf(s[nt][0] - nm0);
            float p1 = __expf(s[nt][1] - nm0);
            float p2 = __expf(s[nt][2] - nm1);
            float p3 = __expf(s[nt][3] - nm1);
            ps0 += p0 + p1;
            ps1 += p2 + p3;
            Pb[r0 * PB_STR + 8 * nt + 2 * tig]           = f2tf32f(p0);
            Pb[r0 * PB_STR + 8 * nt + 2 * tig + 1]       = f2tf32f(p1);
            Pb[(r0 + 8) * PB_STR + 8 * nt + 2 * tig]     = f2tf32f(p2);
            Pb[(r0 + 8) * PB_STR + 8 * nt + 2 * tig + 1] = f2tf32f(p3);
        }
        ps0 += __shfl_xor_sync(0xffffffffu, ps0, 1);
        ps0 += __shfl_xor_sync(0xffffffffu, ps0, 2);
        ps1 += __shfl_xor_sync(0xffffffffu, ps1, 1);
        ps1 += __shfl_xor_sync(0xffffffffu, ps1, 2);
        lr0 = lr0 * corr0 + ps0;
        lr1 = lr1 * corr1 + ps1;
        mr0 = nm0; mr1 = nm1;
        if (tig == 0) {
            rs[16 * w + gid]     = corr0;
            rs[16 * w + gid + 8] = corr1;
        }
        __syncthreads();   // Pb + rs ready for all warps

        // ---- rescale accumulators by per-q correction ----
        float rc[8][2];
#pragma unroll
        for (int nt = 0; nt < 8; ++nt) {
            rc[nt][0] = rs[8 * nt + 2 * tig];
            rc[nt][1] = rs[8 * nt + 2 * tig + 1];
        }
#pragma unroll
        for (int mb = 0; mb < 4; ++mb)
#pragma unroll
            for (int nt = 0; nt < 8; ++nt) {
                acc[mb][nt][0] *= rc[nt][0];
                acc[mb][nt][1] *= rc[nt][1];
                acc[mb][nt][2] *= rc[nt][0];
                acc[mb][nt][3] *= rc[nt][1];
            }

        // ---- O^T += V^T * P^T ----
#pragma unroll
        for (int ks = 0; ks < 8; ++ks) {
            unsigned bp[8][2];
#pragma unroll
            for (int nt = 0; nt < 8; ++nt) {
                const int pr = (8 * nt + gid) * PB_STR + 8 * ks + tig;
                bp[nt][0] = __float_as_uint(Pb[pr]);
                bp[nt][1] = __float_as_uint(Pb[pr + 4]);
            }
#pragma unroll
            for (int mb = 0; mb < 4; ++mb) {
                const int cb = 64 * w + 16 * mb;
                unsigned av[4];
                av[0] = __float_as_uint(Vs[(8 * ks + tig) * VS_STR + cb + gid]);
                av[1] = __float_as_uint(Vs[(8 * ks + tig) * VS_STR + cb + gid + 8]);
                av[2] = __float_as_uint(Vs[(8 * ks + tig + 4) * VS_STR + cb + gid]);
                av[3] = __float_as_uint(Vs[(8 * ks + tig + 4) * VS_STR + cb + gid + 8]);
#pragma unroll
                for (int nt = 0; nt < 8; ++nt)
                    mma_tf32(acc[mb][nt], av, bp[nt][0], bp[nt][1]);
            }
        }
    }

    // ---- epilogue: out[b][c][n] = gamma/l[q] * O^T[c][q] + x[b][c][n] ----
    __syncthreads();
    if (tig == 0) {
        rs[16 * w + gid]     = lr0;
        rs[16 * w + gid + 8] = lr1;
    }
    __syncthreads();
    const float g = gamma[0];
    float fc[8][2];
#pragma unroll
    for (int nt = 0; nt < 8; ++nt) {
        fc[nt][0] = __fdividef(g, rs[8 * nt + 2 * tig]);
        fc[nt][1] = __fdividef(g, rs[8 * nt + 2 * tig + 1]);
    }
#pragma unroll
    for (int mb = 0; mb < 4; ++mb) {
        const int c0 = 64 * w + 16 * mb + gid;
#pragma unroll
        for (int nt = 0; nt < 8; ++nt) {
            const int q = n0 + 8 * nt + 2 * tig;
            const size_t i0 = (size_t)(b * Cc + c0) * Nn + q;
            const size_t i1 = (size_t)(b * Cc + c0 + 8) * Nn + q;
            float2 xv0 = *reinterpret_cast<const float2*>(x + i0);
            float2 xv1 = *reinterpret_cast<const float2*>(x + i1);
            float2 o0, o1;
            o0.x = fmaf(acc[mb][nt][0], fc[nt][0], xv0.x);
            o0.y = fmaf(acc[mb][nt][1], fc[nt][1], xv0.y);
            o1.x = fmaf(acc[mb][nt][2], fc[nt][0], xv1.x);
            o1.y = fmaf(acc[mb][nt][3], fc[nt][1], xv1.y);
            *reinterpret_cast<float2*>(out + i0) = o0;
            *reinterpret_cast<float2*>(out + i1) = o1;
        }
    }
}

// ---------------------------------------------------------------------------
// Launch.  Inputs (metadata order): x, Wq, bq, Wk, bk, Wv, bv, gamma
// ---------------------------------------------------------------------------
extern "C" void kernel_launch(void* const* d_in, const int* in_sizes, int n_in,
                              void* d_out, int out_size)
{
    const float* x     = (const float*)d_in[0];
    const float* Wq    = (const float*)d_in[1];
    const float* bq    = (const float*)d_in[2];
    const float* Wk    = (const float*)d_in[3];
    const float* bk    = (const float*)d_in[4];
    const float* Wv    = (const float*)d_in[5];
    const float* bv    = (const float*)d_in[6];
    const float* gamma = (const float*)d_in[7];
    float* out = (float*)d_out;

    dim3 pgrid(Nn / 64, Oo / 64, Bb);   // 64 x 5 x 4
    proj_kernel<<<pgrid, 256>>>(x, Wq, bq, Wk, bk, Wv, bv);

    cudaFuncSetAttribute(attn_kernel,
                         cudaFuncAttributeMaxDynamicSharedMemorySize, SMEM_BYTES);
    dim3 agrid(Nn / TQ, Bb);            // 64 x 4
    attn_kernel<<<agrid, 128, SMEM_BYTES>>>(x, gamma, out);
}

// round 6
// speedup vs baseline: 5.0826x; 1.1232x over previous
#include <cuda_runtime.h>
#include <cuda_bf16.h>
#include <math.h>

// Problem constants
#define Bb 4
#define Cc 256
#define Nn 4096          // H*W
#define Dd 32            // q/k head dim

// Scratch (bf16): q/k token-major, v channel-major
__device__ __nv_bfloat16 g_q[Bb * Nn * Dd];            // 1 MB
__device__ __nv_bfloat16 g_k[Bb * Nn * Dd];            // 1 MB
__device__ __nv_bfloat16 g_v[(size_t)Bb * Cc * Nn];    // 8 MB

// ---------------------------------------------------------------------------
// bf16 mma: D(16x8) += A(16x16,row) * B(16x8,col), fp32 accum
// ---------------------------------------------------------------------------
__device__ __forceinline__ void mma_bf16(float d[4], const unsigned a[4],
                                         unsigned b0, unsigned b1) {
    asm volatile(
        "mma.sync.aligned.m16n8k16.row.col.f32.bf16.bf16.f32 "
        "{%0,%1,%2,%3}, {%4,%5,%6,%7}, {%8,%9}, {%0,%1,%2,%3};\n"
        : "+f"(d[0]), "+f"(d[1]), "+f"(d[2]), "+f"(d[3])
        : "r"(a[0]), "r"(a[1]), "r"(a[2]), "r"(a[3]), "r"(b0), "r"(b1));
}

__device__ __forceinline__ unsigned pack_bf16x2(float lo, float hi) {
    __nv_bfloat162 h = __floats2bfloat162_rn(lo, hi);   // .x = lo (low 16 bits)
    return *reinterpret_cast<unsigned*>(&h);
}

// ---------------------------------------------------------------------------
// Kernel 1: fused QKV projection (fp32 GEMM, bf16 outputs).
// ---------------------------------------------------------------------------
__global__ __launch_bounds__(256)
void proj_kernel(const float* __restrict__ x,
                 const float* __restrict__ Wq, const float* __restrict__ bq,
                 const float* __restrict__ Wk, const float* __restrict__ bk,
                 const float* __restrict__ Wv, const float* __restrict__ bv)
{
    __shared__ float Xs[32 * 68];
    __shared__ float Ws[32 * 68];

    const int t  = threadIdx.x;
    const int tx = t & 15;
    const int ty = t >> 4;
    const int n0 = blockIdx.x * 64;
    const int o0 = blockIdx.y * 64;
    const int b  = blockIdx.z;

    const float* xb = x + b * Cc * Nn;

    float acc[4][4];
#pragma unroll
    for (int i = 0; i < 4; ++i)
#pragma unroll
        for (int j = 0; j < 4; ++j) acc[i][j] = 0.f;

    for (int kc = 0; kc < Cc; kc += 32) {
#pragma unroll
        for (int i = 0; i < 8; ++i) {
            int idx = t + i * 256;
            int cc  = idx >> 6;
            int nn  = idx & 63;
            Xs[cc * 68 + nn] = xb[(kc + cc) * Nn + n0 + nn];
        }
#pragma unroll
        for (int i = 0; i < 8; ++i) {
            int idx = t + i * 256;
            int oo  = idx >> 5;
            int cc  = idx & 31;
            int o   = o0 + oo;
            const float* wr = (o < 32) ? (Wq + o * Cc)
                             : (o < 64) ? (Wk + (o - 32) * Cc)
                                        : (Wv + (o - 64) * Cc);
            Ws[cc * 68 + oo] = wr[kc + cc];
        }
        __syncthreads();

        const float4* X4 = reinterpret_cast<const float4*>(Xs);
        const float4* W4 = reinterpret_cast<const float4*>(Ws);
#pragma unroll
        for (int cc = 0; cc < 32; ++cc) {
            float4 a = X4[cc * 17 + tx];
            float4 w = W4[cc * 17 + ty];
            acc[0][0] = fmaf(a.x, w.x, acc[0][0]);
            acc[0][1] = fmaf(a.x, w.y, acc[0][1]);
            acc[0][2] = fmaf(a.x, w.z, acc[0][2]);
            acc[0][3] = fmaf(a.x, w.w, acc[0][3]);
            acc[1][0] = fmaf(a.y, w.x, acc[1][0]);
            acc[1][1] = fmaf(a.y, w.y, acc[1][1]);
            acc[1][2] = fmaf(a.y, w.z, acc[1][2]);
            acc[1][3] = fmaf(a.y, w.w, acc[1][3]);
            acc[2][0] = fmaf(a.z, w.x, acc[2][0]);
            acc[2][1] = fmaf(a.z, w.y, acc[2][1]);
            acc[2][2] = fmaf(a.z, w.z, acc[2][2]);
            acc[2][3] = fmaf(a.z, w.w, acc[2][3]);
            acc[3][0] = fmaf(a.w, w.x, acc[3][0]);
            acc[3][1] = fmaf(a.w, w.y, acc[3][1]);
            acc[3][2] = fmaf(a.w, w.z, acc[3][2]);
            acc[3][3] = fmaf(a.w, w.w, acc[3][3]);
        }
        __syncthreads();
    }

    const int o = o0 + ty * 4;
    float4 bias;
    if (o < 32)      bias = *reinterpret_cast<const float4*>(bq + o);
    else if (o < 64) bias = *reinterpret_cast<const float4*>(bk + (o - 32));
    else             bias = *reinterpret_cast<const float4*>(bv + (o - 64));
    float bj[4] = {bias.x, bias.y, bias.z, bias.w};

    if (o < 64) {
        // q/k: token-major rows of 32 bf16
        __nv_bfloat16* dst = (o < 32) ? g_q : g_k;
        const int oc = (o < 32) ? o : (o - 32);
#pragma unroll
        for (int i = 0; i < 4; ++i) {
            int n = n0 + tx * 4 + i;
            uint2 st;
            st.x = pack_bf16x2(acc[i][0] + bj[0], acc[i][1] + bj[1]);
            st.y = pack_bf16x2(acc[i][2] + bj[2], acc[i][3] + bj[3]);
            *reinterpret_cast<uint2*>(dst + ((size_t)b * Nn + n) * Dd + oc) = st;
        }
    } else {
        // v: channel-major [c][n]
        const int c = o - 64;
#pragma unroll
        for (int j = 0; j < 4; ++j) {
            uint2 st;
            st.x = pack_bf16x2(acc[0][j] + bj[j], acc[1][j] + bj[j]);
            st.y = pack_bf16x2(acc[2][j] + bj[j], acc[3][j] + bj[j]);
            *reinterpret_cast<uint2*>(
                g_v + ((size_t)b * Cc + c + j) * Nn + n0 + tx * 4) = st;
        }
    }
}

// ---------------------------------------------------------------------------
// Kernel 2: flash attention, bf16 m16n8k16, no online rescale (fixed shift).
// CTA = 64 queries, 128 threads (4 warps), 2 CTAs/SM.
//   S phase : warp w -> q rows [16w,16w+16) x 64 keys
//   PV phase: warp w -> channels [64w,64w+64), O^T = V^T * P^T
// Smem (bf16 units): Vt[256][72], Ks[64][40], Pb[64][72], ls[64] floats.
// Bank math (word = 4B): Vt/Pb stride 36 words -> lane word 4*gid+tig (distinct)
//                        Ks stride 20 words -> 20*gid+tig mod 32 (distinct)
// ---------------------------------------------------------------------------
#define TQ 64
#define TK 64
#define VT_STR 72
#define KS_STR 40
#define PB_STR 72
#define OFF_KS (256 * VT_STR)             // 18432
#define OFF_PB (OFF_KS + 64 * KS_STR)     // 20992
#define SMEM_BF16 (OFF_PB + 64 * PB_STR)  // 25600
#define SMEM_BYTES (SMEM_BF16 * 2 + 64 * 4)

#define LOG2E 1.44269504f
#define ESHIFT 23.0831204f   // 16 * log2(e): score shift guard

__global__ void __launch_bounds__(128, 2)
attn_kernel(const float* __restrict__ x,
            const float* __restrict__ gamma,
            float* __restrict__ out)
{
    extern __shared__ __nv_bfloat16 smb[];
    __nv_bfloat16* Vt = smb;
    __nv_bfloat16* Ks = smb + OFF_KS;
    __nv_bfloat16* Pb = smb + OFF_PB;
    float* ls = reinterpret_cast<float*>(smb + SMEM_BF16);

    unsigned* VtW = reinterpret_cast<unsigned*>(Vt);
    unsigned* KsW = reinterpret_cast<unsigned*>(Ks);
    unsigned* PbW = reinterpret_cast<unsigned*>(Pb);

    const int t    = threadIdx.x;
    const int w    = t >> 5;
    const int lane = t & 31;
    const int gid  = lane >> 2;
    const int tig  = lane & 3;
    const int n0   = blockIdx.x * TQ;
    const int b    = blockIdx.y;

    // Q fragments: rows r0 = n0+16w+gid, r0+8; halfword cols 2tig(+1)+16ks(+8)
    unsigned qf[2][4];
    {
        const unsigned* q0 = reinterpret_cast<const unsigned*>(
            g_q + ((size_t)b * Nn + n0 + 16 * w + gid) * Dd);
        const unsigned* q1 = q0 + 8 * (Dd / 2);   // +8 rows
#pragma unroll
        for (int ks = 0; ks < 2; ++ks) {
            qf[ks][0] = q0[8 * ks + tig];
            qf[ks][1] = q1[8 * ks + tig];
            qf[ks][2] = q0[8 * ks + tig + 4];
            qf[ks][3] = q1[8 * ks + tig + 4];
        }
    }

    float acc[4][8][4];
#pragma unroll
    for (int mb = 0; mb < 4; ++mb)
#pragma unroll
        for (int nt = 0; nt < 8; ++nt)
#pragma unroll
            for (int j = 0; j < 4; ++j) acc[mb][nt][j] = 0.f;

    float l0 = 0.f, l1 = 0.f;

    const __nv_bfloat16* vb = g_v + (size_t)b * Cc * Nn;
    const __nv_bfloat16* kb = g_k + (size_t)b * Nn * Dd;

    for (int kt = 0; kt < Nn / TK; ++kt) {
        const int mk0 = kt * TK;
        __syncthreads();   // previous tile fully consumed

        // ---- stage Vt[c][key] (copy 64 keys x 256 ch, bf16, coalesced) ----
#pragma unroll
        for (int i = 0; i < 16; ++i) {
            int idx = t + 128 * i;
            int c   = idx >> 3;
            int ch  = idx & 7;          // 8-bf16 chunk along keys
            uint4 v = *reinterpret_cast<const uint4*>(vb + (size_t)c * Nn + mk0 + ch * 8);
            *reinterpret_cast<uint4*>(Vt + c * VT_STR + ch * 8) = v;
        }
        // ---- stage Ks[key][d] (64 x 32 bf16) ----
#pragma unroll
        for (int i = 0; i < 2; ++i) {
            int idx = t + 128 * i;
            int key = idx >> 2;
            int ch  = idx & 3;          // 8-bf16 chunk along d
            uint4 v = *reinterpret_cast<const uint4*>(kb + (size_t)(mk0 + key) * Dd + ch * 8);
            *reinterpret_cast<uint4*>(Ks + key * KS_STR + ch * 8) = v;
        }
        __syncthreads();

        // ---- S = Q K^T : 16 mmas ----
        float s[8][4];
#pragma unroll
        for (int nt = 0; nt < 8; ++nt) {
            s[nt][0] = s[nt][1] = s[nt][2] = s[nt][3] = 0.f;
#pragma unroll
            for (int ks = 0; ks < 2; ++ks) {
                const int kw = (8 * nt + gid) * (KS_STR / 2) + 8 * ks + tig;
                mma_bf16(s[nt], qf[ks], KsW[kw], KsW[kw + 4]);
            }
        }

        // ---- exp (fixed shift, no running max) + P -> smem bf16 ----
        float ps0 = 0.f, ps1 = 0.f;
        const int r0 = 16 * w + gid;
#pragma unroll
        for (int nt = 0; nt < 8; ++nt) {
            float p0 = exp2f(fmaf(s[nt][0], LOG2E, -ESHIFT));
            float p1 = exp2f(fmaf(s[nt][1], LOG2E, -ESHIFT));
            float p2 = exp2f(fmaf(s[nt][2], LOG2E, -ESHIFT));
            float p3 = exp2f(fmaf(s[nt][3], LOG2E, -ESHIFT));
            ps0 += p0 + p1;
            ps1 += p2 + p3;
            PbW[r0 * (PB_STR / 2) + 4 * nt + tig]       = pack_bf16x2(p0, p1);
            PbW[(r0 + 8) * (PB_STR / 2) + 4 * nt + tig] = pack_bf16x2(p2, p3);
        }
        ps0 += __shfl_xor_sync(0xffffffffu, ps0, 1);
        ps0 += __shfl_xor_sync(0xffffffffu, ps0, 2);
        ps1 += __shfl_xor_sync(0xffffffffu, ps1, 1);
        ps1 += __shfl_xor_sync(0xffffffffu, ps1, 2);
        l0 += ps0;
        l1 += ps1;
        __syncthreads();   // Pb ready

        // ---- O^T += V^T P^T : 128 mmas ----
#pragma unroll
        for (int ks = 0; ks < 4; ++ks) {
            unsigned bp[8][2];
#pragma unroll
            for (int nt = 0; nt < 8; ++nt) {
                const int pw = (8 * nt + gid) * (PB_STR / 2) + 8 * ks + tig;
                bp[nt][0] = PbW[pw];
                bp[nt][1] = PbW[pw + 4];
            }
#pragma unroll
            for (int mb = 0; mb < 4; ++mb) {
                const int c0 = 64 * w + 16 * mb + gid;
                unsigned av[4];
                const int aw = c0 * (VT_STR / 2) + 8 * ks + tig;
                av[0] = VtW[aw];
                av[1] = VtW[aw + 8 * (VT_STR / 2)];
                av[2] = VtW[aw + 4];
                av[3] = VtW[aw + 8 * (VT_STR / 2) + 4];
#pragma unroll
                for (int nt = 0; nt < 8; ++nt)
                    mma_bf16(acc[mb][nt], av, bp[nt][0], bp[nt][1]);
            }
        }
    }

    // ---- epilogue: out = gamma/l * O^T + x ----
    __syncthreads();
    if (tig == 0) {
        ls[16 * w + gid]     = l0;
        ls[16 * w + gid + 8] = l1;
    }
    __syncthreads();
    const float g = gamma[0];
    float fc[8][2];
#pragma unroll
    for (int nt = 0; nt < 8; ++nt) {
        fc[nt][0] = __fdividef(g, ls[8 * nt + 2 * tig]);
        fc[nt][1] = __fdividef(g, ls[8 * nt + 2 * tig + 1]);
    }
#pragma unroll
    for (int mb = 0; mb < 4; ++mb) {
        const int c0 = 64 * w + 16 * mb + gid;
#pragma unroll
        for (int nt = 0; nt < 8; ++nt) {
            const int q = n0 + 8 * nt + 2 * tig;
            const size_t i0 = (size_t)(b * Cc + c0) * Nn + q;
            const size_t i1 = (size_t)(b * Cc + c0 + 8) * Nn + q;
            float2 xv0 = *reinterpret_cast<const float2*>(x + i0);
            float2 xv1 = *reinterpret_cast<const float2*>(x + i1);
            float2 o0, o1;
            o0.x = fmaf(acc[mb][nt][0], fc[nt][0], xv0.x);
            o0.y = fmaf(acc[mb][nt][1], fc[nt][1], xv0.y);
            o1.x = fmaf(acc[mb][nt][2], fc[nt][0], xv1.x);
            o1.y = fmaf(acc[mb][nt][3], fc[nt][1], xv1.y);
            *reinterpret_cast<float2*>(out + i0) = o0;
            *reinterpret_cast<float2*>(out + i1) = o1;
        }
    }
}

// ---------------------------------------------------------------------------
// Launch.  Inputs (metadata order): x, Wq, bq, Wk, bk, Wv, bv, gamma
// ---------------------------------------------------------------------------
extern "C" void kernel_launch(void* const* d_in, const int* in_sizes, int n_in,
                              void* d_out, int out_size)
{
    const float* x     = (const float*)d_in[0];
    const float* Wq    = (const float*)d_in[1];
    const float* bq    = (const float*)d_in[2];
    const float* Wk    = (const float*)d_in[3];
    const float* bk    = (const float*)d_in[4];
    const float* Wv    = (const float*)d_in[5];
    const float* bv    = (const float*)d_in[6];
    const float* gamma = (const float*)d_in[7];
    float* out = (float*)d_out;

    dim3 pgrid(Nn / 64, (Cc + 64) / 64, Bb);   // 64 x 5 x 4
    proj_kernel<<<pgrid, 256>>>(x, Wq, bq, Wk, bk, Wv, bv);

    cudaFuncSetAttribute(attn_kernel,
                         cudaFuncAttributeMaxDynamicSharedMemorySize, SMEM_BYTES);
    dim3 agrid(Nn / TQ, Bb);                   // 64 x 4
    attn_kernel<<<agrid, 128, SMEM_BYTES>>>(x, gamma, out);
}